// round 9
// baseline (speedup 1.0000x reference)
#include <cuda_runtime.h>
#include <cuda_bf16.h>
#include <cstdint>

#define DI __device__ __forceinline__

// Problem shape (fixed by the dataset)
static constexpr int M_TOTAL = 8192;   // B*S
static constexpr int N_TOTAL = 4096;
static constexpr int K_TOTAL = 1024;

// Scratch: harness promotes int8 jax arrays to int32 buffers; we pre-pack both
// a bf16 image (HMMA warps, exact: int8 fits bf16 significand, fp32 acc < 2^24)
// and an int8 image (dp4a warps, exact int32 accumulation).
__device__ __align__(16) uint16_t g_xh[(size_t)M_TOTAL * K_TOTAL];   // 16 MB
__device__ __align__(16) uint16_t g_wh[(size_t)N_TOTAL * K_TOTAL];   // 8 MB
__device__ __align__(16) int8_t   g_x8[(size_t)M_TOTAL * K_TOTAL];   // 8 MB
__device__ __align__(16) int8_t   g_w8[(size_t)N_TOTAL * K_TOTAL];   // 4 MB

// Tiling: CTA covers 128(M) x 256(N). Rows 0-95 via HMMA (12 warps, 3Mx4N,
// 32x64 warp tiles); rows 96-127 via dp4a (4 warps, one per SMSP, 8 rows each).
static constexpr int TILE_M  = 128;
static constexpr int TILE_N  = 256;
static constexpr int KSTAGE  = 64;                   // K elems per stage
static constexpr int NCHUNK  = K_TOTAL / KSTAGE;     // 16
static constexpr int NSTAGES = 3;
static constexpr int THREADS = 512;                  // 16 warps

// SMEM layout
static constexpr int ROW_B   = 144;                  // bf16 row pad 128->144B
static constexpr int A_ST    = 96 * ROW_B;           // 13824
static constexpr int B_ST    = 256 * ROW_B;          // 36864
static constexpr int A8_ST   = 16 * 132;             // 2112  (transposed [g][r32], pad 132)
static constexpr int B8_ST   = 16 * 1028;            // 16448 (transposed [g][col], pad 1028)
static constexpr int OFF_A   = 0;
static constexpr int OFF_B   = NSTAGES * A_ST;                    // 41472
static constexpr int OFF_A8  = OFF_B + NSTAGES * B_ST;            // 152064
static constexpr int OFF_B8  = OFF_A8 + NSTAGES * A8_ST;          // 158400
static constexpr int SM_BYTES = OFF_B8 + NSTAGES * B8_ST;         // 207744

DI uint32_t smem_u32(const void* p) {
    uint32_t a;
    asm("{ .reg .u64 t; cvta.to.shared.u64 t, %1; cvt.u32.u64 %0, t; }" : "=r"(a) : "l"(p));
    return a;
}
DI void cp16(uint32_t dst, const void* src) {
    asm volatile("cp.async.cg.shared.global [%0], [%1], 16;" :: "r"(dst), "l"(src));
}
#define CP_COMMIT() asm volatile("cp.async.commit_group;" ::: "memory")
#define CP_WAIT1()  asm volatile("cp.async.wait_group 1;" ::: "memory")

DI uint32_t lds32(uint32_t a) {
    uint32_t v;
    asm volatile("ld.shared.b32 %0, [%1];" : "=r"(v) : "r"(a));
    return v;
}
DI void sts32(uint32_t a, uint32_t v) {
    asm volatile("st.shared.b32 [%0], %1;" :: "r"(a), "r"(v) : "memory");
}
DI void ldsm4(uint32_t* r, uint32_t addr) {
    asm volatile("ldmatrix.sync.aligned.m8n8.x4.shared.b16 {%0,%1,%2,%3}, [%4];"
                 : "=r"(r[0]), "=r"(r[1]), "=r"(r[2]), "=r"(r[3]) : "r"(addr));
}
DI void mma_bf16(float* c, const uint32_t* a, uint32_t b0, uint32_t b1) {
    asm volatile(
        "mma.sync.aligned.m16n8k16.row.col.f32.bf16.bf16.f32 "
        "{%0,%1,%2,%3}, {%4,%5,%6,%7}, {%8,%9}, {%0,%1,%2,%3};"
        : "+f"(c[0]), "+f"(c[1]), "+f"(c[2]), "+f"(c[3])
        : "r"(a[0]), "r"(a[1]), "r"(a[2]), "r"(a[3]), "r"(b0), "r"(b1));
}

// ---------------- Pack pre-pass: int32 -> bf16 AND int8, 8 elems/thread ----------------
DI uint32_t bf16x2_from_ints(int lo, int hi) {
    uint32_t r;
    asm("cvt.rn.bf16x2.f32 %0, %1, %2;" : "=r"(r) : "f"((float)hi), "f"((float)lo));
    return r;
}
DI uint32_t pack4(int4 v) {
    return (uint32_t)(v.x & 0xFF) | ((uint32_t)(v.y & 0xFF) << 8) |
           ((uint32_t)(v.z & 0xFF) << 16) | ((uint32_t)v.w << 24);
}
__global__ void pack_both(const int4* __restrict__ xs, const int4* __restrict__ ws,
                          uint16_t* __restrict__ xh, uint16_t* __restrict__ wh,
                          int8_t* __restrict__ x8, int8_t* __restrict__ w8,
                          int n8x, int n8w) {
    int i = blockIdx.x * blockDim.x + threadIdx.x;
    const int4* src; uint16_t* dh; int8_t* d8; int j;
    if (i < n8w) { src = ws; dh = wh; d8 = w8; j = i; }
    else if (i - n8w < n8x) { src = xs; dh = xh; d8 = x8; j = i - n8w; }
    else return;
    int4 v0 = src[(size_t)j * 2 + 0];
    int4 v1 = src[(size_t)j * 2 + 1];
    uint4 oh;
    oh.x = bf16x2_from_ints(v0.x, v0.y);
    oh.y = bf16x2_from_ints(v0.z, v0.w);
    oh.z = bf16x2_from_ints(v1.x, v1.y);
    oh.w = bf16x2_from_ints(v1.z, v1.w);
    reinterpret_cast<uint4*>(dh)[j] = oh;
    uint2 o8;
    o8.x = pack4(v0); o8.y = pack4(v1);
    reinterpret_cast<uint2*>(d8)[j] = o8;
}

// bf16 tiles: A 96 rows + B 256 rows, 128B/row, via cp.async.
DI void load_stage_bf16(const uint16_t* __restrict__ x, const uint16_t* __restrict__ w,
                        int m0, int n0, int kc, uint32_t sbase, int stage, int tid) {
    const uint32_t smA = sbase + OFF_A + stage * A_ST;
    const uint32_t smB = sbase + OFF_B + stage * B_ST;
    const int k0 = kc * KSTAGE;
#pragma unroll
    for (int i = 0; i < 2; i++) {                    // A: 96*8=768 chunks
        int u = tid + i * THREADS;
        if (u < 768) {
            int row = u >> 3, c = u & 7;
            cp16(smA + row * ROW_B + c * 16, x + (size_t)(m0 + row) * K_TOTAL + k0 + c * 8);
        }
    }
#pragma unroll
    for (int i = 0; i < 4; i++) {                    // B: 256*8=2048 chunks
        int u = tid + i * THREADS;
        int row = u >> 3, c = u & 7;
        cp16(smB + row * ROW_B + c * 16, w + (size_t)(n0 + row) * K_TOTAL + k0 + c * 8);
    }
}

__global__ void __launch_bounds__(THREADS, 1)
qgemm_hybrid_kernel(const float* __restrict__ scale_i, const float* __restrict__ scale_w,
                    const float* __restrict__ bias, float* __restrict__ out) {
    extern __shared__ char smem[];
    const uint16_t* __restrict__ xh = g_xh;
    const uint16_t* __restrict__ wh = g_wh;
    const int8_t*  __restrict__ x8 = g_x8;
    const int8_t*  __restrict__ w8 = g_w8;
    const uint32_t sbase = smem_u32(smem);
    const int tid  = threadIdx.x;
    const int lane = tid & 31;
    const int wid  = tid >> 5;
    const int m0 = blockIdx.y * TILE_M;
    const int n0 = blockIdx.x * TILE_N;

    // Int8 fill indices (all 512 threads participate in fills)
    const int fa_r32 = tid >> 4;                 // 0..31 -> row m0+96+r32
    const int f_g    = tid & 15;                 // k-group within stage

    // ---- Prologue ----
    load_stage_bf16(xh, wh, m0, n0, 0, sbase, 0, tid); CP_COMMIT();
    load_stage_bf16(xh, wh, m0, n0, 1, sbase, 1, tid); CP_COMMIT();
    {   // int8 stage 0 (direct LDG+STS; one-time stall is fine)
        uint32_t va = *reinterpret_cast<const uint32_t*>(
            x8 + (size_t)(m0 + 96 + fa_r32) * K_TOTAL + f_g * 4);
        uint32_t vb[8];
#pragma unroll
        for (int p = 0; p < 8; p++) {
            int col = p * 32 + fa_r32;
            vb[p] = *reinterpret_cast<const uint32_t*>(
                w8 + (size_t)(n0 + col) * K_TOTAL + f_g * 4);
        }
        sts32(sbase + OFF_A8 + f_g * 132 + fa_r32 * 4, va);
#pragma unroll
        for (int p = 0; p < 8; p++)
            sts32(sbase + OFF_B8 + f_g * 1028 + (p * 32 + fa_r32) * 4, vb[p]);
    }

    // Role split
    const bool is_dp = (wid >= 12);
    // HMMA warps: warp_m = wid>>2 (0..2), warp_n = wid&3 (0..3); SMSP = wid&3.
    const int warp_m = wid >> 2;
    const int warp_n = wid & 3;
    const int am = lane >> 3;
    const uint32_t aOff = (uint32_t)(warp_m * 32 + (am & 1) * 8 + (lane & 7)) * ROW_B
                        + (uint32_t)(am >> 1) * 16;
    const uint32_t bOff = (uint32_t)(warp_n * 64 + (am >> 1) * 8 + (lane & 7)) * ROW_B
                        + (uint32_t)(am & 1) * 16;
    // dp4a warps: wd 0..3 (SMSP 0..3), rows m0+96+8*wd .. +7, cols lane+32c.
    const int wd = wid - 12;

    float facc[2][8][4];
    int   iacc[8][8];
    if (!is_dp) {
#pragma unroll
        for (int mt = 0; mt < 2; mt++)
#pragma unroll
            for (int nt = 0; nt < 8; nt++)
#pragma unroll
                for (int j = 0; j < 4; j++) facc[mt][nt][j] = 0.0f;
    } else {
#pragma unroll
        for (int r = 0; r < 8; r++)
#pragma unroll
            for (int c = 0; c < 8; c++) iacc[r][c] = 0;
    }

#pragma unroll 1
    for (int kc = 0; kc < NCHUNK; kc++) {
        CP_WAIT1();                    // bf16 stage kc resident
        __syncthreads();               // gates bf16 kc + int8 kc (STS last iter)
        if (kc + 2 < NCHUNK)
            load_stage_bf16(xh, wh, m0, n0, kc + 2, sbase, (kc + 2) % NSTAGES, tid);
        CP_COMMIT();

        // Early LDG of int8 for stage kc+1 (latency hides under compute below)
        const int kn = (kc + 1 < NCHUNK) ? kc + 1 : kc;
        const int k0n = kn * KSTAGE;
        uint32_t va = *reinterpret_cast<const uint32_t*>(
            x8 + (size_t)(m0 + 96 + fa_r32) * K_TOTAL + k0n + f_g * 4);
        uint32_t vb[8];
#pragma unroll
        for (int p = 0; p < 8; p++) {
            int col = p * 32 + fa_r32;
            vb[p] = *reinterpret_cast<const uint32_t*>(
                w8 + (size_t)(n0 + col) * K_TOTAL + k0n + f_g * 4);
        }

        const int stage = kc % NSTAGES;
        if (!is_dp) {
            // ---- HMMA compute: 32x64 warp tile over K=64 ----
            const uint32_t aS = sbase + OFF_A + stage * A_ST + aOff;
            const uint32_t bS = sbase + OFF_B + stage * B_ST + bOff;
#pragma unroll
            for (int ks = 0; ks < 4; ks++) {
                const uint32_t ko = ks * 32;
                uint32_t a[2][4];
                ldsm4(a[0], aS + ko);
                ldsm4(a[1], aS + 16 * ROW_B + ko);
#pragma unroll
                for (int p = 0; p < 4; p++) {
                    uint32_t b[4];
                    ldsm4(b, bS + (uint32_t)p * 16 * ROW_B + ko);
                    mma_bf16(facc[0][2 * p + 0], a[0], b[0], b[1]);
                    mma_bf16(facc[1][2 * p + 0], a[1], b[0], b[1]);
                    mma_bf16(facc[0][2 * p + 1], a[0], b[2], b[3]);
                    mma_bf16(facc[1][2 * p + 1], a[1], b[2], b[3]);
                }
            }
        } else {
            // ---- dp4a compute: 8 rows x 256 cols over K=64 ----
            const uint32_t a8 = sbase + OFF_A8 + stage * A8_ST + (uint32_t)(8 * wd) * 4;
            const uint32_t b8 = sbase + OFF_B8 + stage * B8_ST + (uint32_t)lane * 4;
#pragma unroll 4
            for (int g = 0; g < 16; g++) {
                int av[8], bv[8];
#pragma unroll
                for (int r = 0; r < 8; r++) av[r] = (int)lds32(a8 + g * 132 + r * 4);   // broadcast
#pragma unroll
                for (int c = 0; c < 8; c++) bv[c] = (int)lds32(b8 + g * 1028 + c * 128); // conflict-free
#pragma unroll
                for (int r = 0; r < 8; r++)
#pragma unroll
                    for (int c = 0; c < 8; c++)
                        iacc[r][c] = __dp4a(av[r], bv[c], iacc[r][c]);
            }
        }

        // Late STS of int8 stage kc+1 (visible after next loop-top sync)
        const int nst = (kc + 1) % NSTAGES;
        sts32(sbase + OFF_A8 + nst * A8_ST + f_g * 132 + fa_r32 * 4, va);
#pragma unroll
        for (int p = 0; p < 8; p++)
            sts32(sbase + OFF_B8 + nst * B8_ST + f_g * 1028 + (p * 32 + fa_r32) * 4, vb[p]);
    }

    // ---- Epilogue: out = acc * (scale_i * scale_w[n]) + bias[n] (exact ints in acc) ----
    const float si = __ldg(scale_i);
    if (!is_dp) {
        const int tg = lane >> 2, tc = lane & 3;
        const int row0 = m0 + warp_m * 32 + tg;
        const int col0 = n0 + warp_n * 64 + tc * 2;
#pragma unroll
        for (int nt = 0; nt < 8; nt++) {
            const int c = col0 + nt * 8;
            const float2 sw = __ldg(reinterpret_cast<const float2*>(scale_w + c));
            const float2 bb = __ldg(reinterpret_cast<const float2*>(bias + c));
            const float s0 = si * sw.x, s1 = si * sw.y;
#pragma unroll
            for (int mt = 0; mt < 2; mt++) {
                const int r = row0 + mt * 16;
                float2 o0, o1;
                o0.x = fmaf(facc[mt][nt][0], s0, bb.x);
                o0.y = fmaf(facc[mt][nt][1], s1, bb.y);
                o1.x = fmaf(facc[mt][nt][2], s0, bb.x);
                o1.y = fmaf(facc[mt][nt][3], s1, bb.y);
                *reinterpret_cast<float2*>(out + (size_t)r * N_TOTAL + c)       = o0;
                *reinterpret_cast<float2*>(out + (size_t)(r + 8) * N_TOTAL + c) = o1;
            }
        }
    } else {
        const int row0 = m0 + 96 + 8 * wd;
#pragma unroll
        for (int c = 0; c < 8; c++) {
            const int cc = n0 + lane + 32 * c;
            const float s = si * __ldg(scale_w + cc);
            const float b = __ldg(bias + cc);
#pragma unroll
            for (int r = 0; r < 8; r++)
                out[(size_t)(row0 + r) * N_TOTAL + cc] = fmaf((float)iacc[r][c], s, b);
        }
    }
}

extern "C" void kernel_launch(void* const* d_in, const int* in_sizes, int n_in,
                              void* d_out, int out_size) {
    const int4* x32 = (const int4*)d_in[0];      // [8192,1024] int32 (int8 values)
    const int4* w32 = (const int4*)d_in[1];      // [4096,1024] int32
    const float* si = (const float*)d_in[2];
    const float* sw = (const float*)d_in[3];
    const float* bi = (const float*)d_in[4];
    float* out = (float*)d_out;

    uint16_t *dxh = nullptr, *dwh = nullptr;
    int8_t *dx8 = nullptr, *dw8 = nullptr;
    cudaGetSymbolAddress((void**)&dxh, g_xh);
    cudaGetSymbolAddress((void**)&dwh, g_wh);
    cudaGetSymbolAddress((void**)&dx8, g_x8);
    cudaGetSymbolAddress((void**)&dw8, g_w8);

    {
        int n8x = (M_TOTAL * K_TOTAL) / 8;
        int n8w = (N_TOTAL * K_TOTAL) / 8;
        int total = n8x + n8w;
        pack_both<<<(total + 255) / 256, 256>>>(x32, w32, dxh, dwh, dx8, dw8, n8x, n8w);
    }

    cudaFuncSetAttribute(qgemm_hybrid_kernel,
                         cudaFuncAttributeMaxDynamicSharedMemorySize, SM_BYTES);
    dim3 grid(N_TOTAL / TILE_N, M_TOTAL / TILE_M);  // (16, 64)
    qgemm_hybrid_kernel<<<grid, THREADS, SM_BYTES, 0>>>(si, sw, bi, out);
}

// round 10
// speedup vs baseline: 2.9394x; 2.9394x over previous
#include <cuda_runtime.h>
#include <cuda_bf16.h>
#include <cstdint>

#define DI __device__ __forceinline__

// Problem shape (fixed by the dataset)
static constexpr int M_TOTAL = 8192;   // B*S = 4*2048
static constexpr int N_TOTAL = 4096;
static constexpr int K_TOTAL = 1024;

// bf16 scratch (harness promotes int8 jax arrays to int32 buffers; int8 values
// are exact in bf16, fp32 accumulation exact: |acc| <= 127*127*1024 < 2^24)
__device__ __align__(16) uint16_t g_xh[(size_t)M_TOTAL * K_TOTAL];   // 16 MB
__device__ __align__(16) uint16_t g_wh[(size_t)N_TOTAL * K_TOTAL];   // 8 MB

// Tiling: CTA 128x128, 8 warps (4M x 2N), warp tile 32x64.
// 2 CTAs co-resident per SM -> phase-interleaved: one CTA's MMAs cover the
// other's CP_WAIT/__syncthreads/load bubbles.
static constexpr int TILE_M  = 128;
static constexpr int TILE_N  = 128;
static constexpr int KSTAGE  = 64;                   // K elems per stage (128 B/row)
static constexpr int NCHUNK  = K_TOTAL / KSTAGE;     // 16
static constexpr int NSTAGES = 3;
static constexpr int THREADS = 256;                  // 8 warps

// SMEM: bf16 tiles, rows padded 128B -> 144B (9x16B stride => conflict-free ldmatrix)
static constexpr int ROW_B   = 144;
static constexpr int A_STAGE = TILE_M * ROW_B;       // 18432 B
static constexpr int B_STAGE = TILE_N * ROW_B;       // 18432 B
static constexpr int SM_B0   = NSTAGES * A_STAGE;
static constexpr int SM_BYTES = NSTAGES * (A_STAGE + B_STAGE);  // 110592 B (x2 = 221184 <= 228K)

DI uint32_t smem_u32(const void* p) {
    uint32_t a;
    asm("{ .reg .u64 t; cvta.to.shared.u64 t, %1; cvt.u32.u64 %0, t; }" : "=r"(a) : "l"(p));
    return a;
}
DI void cp16(uint32_t dst, const void* src) {
    asm volatile("cp.async.cg.shared.global [%0], [%1], 16;" :: "r"(dst), "l"(src));
}
#define CP_COMMIT() asm volatile("cp.async.commit_group;" ::: "memory")
#define CP_WAIT1()  asm volatile("cp.async.wait_group 1;" ::: "memory")

DI void ldsm4(uint32_t* r, uint32_t addr) {
    asm volatile("ldmatrix.sync.aligned.m8n8.x4.shared.b16 {%0,%1,%2,%3}, [%4];"
                 : "=r"(r[0]), "=r"(r[1]), "=r"(r[2]), "=r"(r[3]) : "r"(addr));
}

// HMMA bf16: D(f32) = A(bf16,row 16x16) * B(bf16,col 16x8) + D
DI void mma_bf16(float* c, const uint32_t* a, uint32_t b0, uint32_t b1) {
    asm volatile(
        "mma.sync.aligned.m16n8k16.row.col.f32.bf16.bf16.f32 "
        "{%0,%1,%2,%3}, {%4,%5,%6,%7}, {%8,%9}, {%0,%1,%2,%3};"
        : "+f"(c[0]), "+f"(c[1]), "+f"(c[2]), "+f"(c[3])
        : "r"(a[0]), "r"(a[1]), "r"(a[2]), "r"(a[3]), "r"(b0), "r"(b1));
}

// ---------------- Pack pre-pass: int32 -> bf16, 8 elements/thread ----------------
DI uint32_t bf16x2_from_ints(int lo, int hi) {
    uint32_t r;
    asm("cvt.rn.bf16x2.f32 %0, %1, %2;" : "=r"(r) : "f"((float)hi), "f"((float)lo));
    return r;
}
DI uint4 pack8(const int4* p) {
    int4 v0 = p[0], v1 = p[1];
    uint4 o;
    o.x = bf16x2_from_ints(v0.x, v0.y);
    o.y = bf16x2_from_ints(v0.z, v0.w);
    o.z = bf16x2_from_ints(v1.x, v1.y);
    o.w = bf16x2_from_ints(v1.z, v1.w);
    return o;
}
__global__ void pack_both(const int4* __restrict__ xs, const int4* __restrict__ ws,
                          uint16_t* __restrict__ xd, uint16_t* __restrict__ wd,
                          int n8x, int n8w) {
    int i = blockIdx.x * blockDim.x + threadIdx.x;
    if (i < n8w) {
        reinterpret_cast<uint4*>(wd)[i] = pack8(ws + (size_t)i * 2);
    } else if (i - n8w < n8x) {
        int j = i - n8w;
        reinterpret_cast<uint4*>(xd)[j] = pack8(xs + (size_t)j * 2);
    }
}

// Load one K-stage: A 128 rows + B 128 rows, 128B/row, via cp.async (4+4 per thread).
DI void load_stage(const uint16_t* __restrict__ x, const uint16_t* __restrict__ w,
                   int m0, int n0, int kc, uint32_t sbase, int stage, int tid) {
    const uint32_t smA = sbase + stage * A_STAGE;
    const uint32_t smB = sbase + SM_B0 + stage * B_STAGE;
    const int k0 = kc * KSTAGE;
#pragma unroll
    for (int i = 0; i < 4; i++) {                    // A: 1024 16B-chunks, 4/thread
        int u = tid + i * THREADS;
        int row = u >> 3, c = u & 7;
        cp16(smA + row * ROW_B + c * 16, x + (size_t)(m0 + row) * K_TOTAL + k0 + c * 8);
    }
#pragma unroll
    for (int i = 0; i < 4; i++) {                    // B: 1024 16B-chunks, 4/thread
        int u = tid + i * THREADS;
        int row = u >> 3, c = u & 7;
        cp16(smB + row * ROW_B + c * 16, w + (size_t)(n0 + row) * K_TOTAL + k0 + c * 8);
    }
}

__global__ void __launch_bounds__(THREADS, 2)
qgemm_hmma_kernel(const float* __restrict__ scale_i, const float* __restrict__ scale_w,
                  const float* __restrict__ bias, float* __restrict__ out) {
    extern __shared__ char smem[];
    const uint16_t* __restrict__ x = g_xh;
    const uint16_t* __restrict__ w = g_wh;
    const uint32_t sbase = smem_u32(smem);
    const int tid = threadIdx.x;
    const int lane = tid & 31;
    const int wid = tid >> 5;
    const int warp_m = wid & 3;        // 4 warps along M: 32 rows each
    const int warp_n = wid >> 2;       // 2 warps along N: 64 cols each
    const int m0 = blockIdx.y * TILE_M;
    const int n0 = blockIdx.x * TILE_N;

    const int tg = lane >> 2;          // groupID (0..7)
    const int tc = lane & 3;           // threadID_in_group

    float acc[2][8][4];
#pragma unroll
    for (int mt = 0; mt < 2; mt++)
#pragma unroll
        for (int nt = 0; nt < 8; nt++)
#pragma unroll
            for (int j = 0; j < 4; j++) acc[mt][nt][j] = 0.0f;

    // ldmatrix lane addressing (within a stage, before k-step offset):
    // A x4: [rows 0-7, k0-7][rows 8-15, k0-7][rows 0-7, k8-15][rows 8-15, k8-15]
    const int am = lane >> 3;
    const uint32_t aOff = (uint32_t)(warp_m * 32 + (am & 1) * 8 + (lane & 7)) * ROW_B
                        + (uint32_t)(am >> 1) * 16;
    // B x4 per n-tile pair p: [n 0-7, k0-7][n 0-7, k8-15][n 8-15, k0-7][n 8-15, k8-15]
    const uint32_t bOff = (uint32_t)(warp_n * 64 + (am >> 1) * 8 + (lane & 7)) * ROW_B
                        + (uint32_t)(am & 1) * 16;

    // Prologue: stages 0,1 in flight
    load_stage(x, w, m0, n0, 0, sbase, 0, tid); CP_COMMIT();
    load_stage(x, w, m0, n0, 1, sbase, 1, tid); CP_COMMIT();

#pragma unroll 1
    for (int kc = 0; kc < NCHUNK; kc++) {
        CP_WAIT1();                    // stage kc resident
        __syncthreads();               // all warps done with stage (kc+2)%3's old data
        if (kc + 2 < NCHUNK)
            load_stage(x, w, m0, n0, kc + 2, sbase, (kc + 2) % NSTAGES, tid);
        CP_COMMIT();

        const int stage = kc % NSTAGES;
        const uint32_t aS = sbase + stage * A_STAGE + aOff;
        const uint32_t bS = sbase + SM_B0 + stage * B_STAGE + bOff;
#pragma unroll
        for (int ks = 0; ks < 4; ks++) {           // four k=16 steps per stage
            const uint32_t ko = ks * 32;           // 16 bf16 = 32 bytes
            uint32_t a[2][4];
            ldsm4(a[0], aS + ko);
            ldsm4(a[1], aS + 16 * ROW_B + ko);
#pragma unroll
            for (int p = 0; p < 4; p++) {          // n-tile pairs (2p, 2p+1)
                uint32_t b[4];
                ldsm4(b, bS + (uint32_t)p * 16 * ROW_B + ko);
                mma_bf16(acc[0][2 * p + 0], a[0], b[0], b[1]);
                mma_bf16(acc[1][2 * p + 0], a[1], b[0], b[1]);
                mma_bf16(acc[0][2 * p + 1], a[0], b[2], b[3]);
                mma_bf16(acc[1][2 * p + 1], a[1], b[2], b[3]);
            }
        }
    }

    // Epilogue: out = acc * (scale_i * scale_w[n]) + bias[n]  (acc holds exact integers)
    const float si = __ldg(scale_i);
    const int row0 = m0 + warp_m * 32 + tg;
    const int col0 = n0 + warp_n * 64 + tc * 2;
#pragma unroll
    for (int nt = 0; nt < 8; nt++) {
        const int c = col0 + nt * 8;
        const float2 sw = __ldg(reinterpret_cast<const float2*>(scale_w + c));
        const float2 bb = __ldg(reinterpret_cast<const float2*>(bias + c));
        const float s0 = si * sw.x, s1 = si * sw.y;
#pragma unroll
        for (int mt = 0; mt < 2; mt++) {
            const int r = row0 + mt * 16;
            float2 o0, o1;
            o0.x = fmaf(acc[mt][nt][0], s0, bb.x);
            o0.y = fmaf(acc[mt][nt][1], s1, bb.y);
            o1.x = fmaf(acc[mt][nt][2], s0, bb.x);
            o1.y = fmaf(acc[mt][nt][3], s1, bb.y);
            *reinterpret_cast<float2*>(out + (size_t)r * N_TOTAL + c)       = o0;
            *reinterpret_cast<float2*>(out + (size_t)(r + 8) * N_TOTAL + c) = o1;
        }
    }
}

extern "C" void kernel_launch(void* const* d_in, const int* in_sizes, int n_in,
                              void* d_out, int out_size) {
    // Harness promotes int8 jax arrays to int32 buffers.
    const int4* x32 = (const int4*)d_in[0];      // [8192,1024] int32 (int8 values)
    const int4* w32 = (const int4*)d_in[1];      // [4096,1024] int32
    const float* si = (const float*)d_in[2];     // scalar f32
    const float* sw = (const float*)d_in[3];     // [4096] f32
    const float* bi = (const float*)d_in[4];     // [4096] f32
    float* out = (float*)d_out;                  // [8192,4096] f32

    uint16_t *dxh = nullptr, *dwh = nullptr;
    cudaGetSymbolAddress((void**)&dxh, g_xh);
    cudaGetSymbolAddress((void**)&dwh, g_wh);

    {
        int n8x = (M_TOTAL * K_TOTAL) / 8;       // 1048576
        int n8w = (N_TOTAL * K_TOTAL) / 8;       // 524288
        int total = n8x + n8w;
        pack_both<<<(total + 255) / 256, 256>>>(x32, w32, dxh, dwh, n8x, n8w);
    }

    cudaFuncSetAttribute(qgemm_hmma_kernel,
                         cudaFuncAttributeMaxDynamicSharedMemorySize, SM_BYTES);
    dim3 grid(N_TOTAL / TILE_N, M_TOTAL / TILE_M);  // (32, 64)
    qgemm_hmma_kernel<<<grid, THREADS, SM_BYTES, 0>>>(si, sw, bi, out);
}

// round 13
// speedup vs baseline: 2.9403x; 1.0003x over previous
#include <cuda_runtime.h>
#include <cuda_bf16.h>
#include <cstdint>

#define DI __device__ __forceinline__

// Problem shape (fixed by the dataset)
static constexpr int M_TOTAL = 8192;   // B*S = 4*2048
static constexpr int N_TOTAL = 4096;
static constexpr int K_TOTAL = 1024;

// bf16 scratch (harness promotes int8 jax arrays to int32 buffers; int8 values
// are exact in bf16, fp32 accumulation exact: |acc| <= 127*127*1024 < 2^24)
__device__ __align__(16) uint16_t g_xh[(size_t)M_TOTAL * K_TOTAL];   // 16 MB
__device__ __align__(16) uint16_t g_wh[(size_t)N_TOTAL * K_TOTAL];   // 8 MB

// Tiling: CTA 128x128, 8 warps (4M x 2N), warp tile 32x64.
// 2 CTAs co-resident per SM: phase-interleaved so one CTA's MMAs cover the
// other's CP_WAIT/__syncthreads/load bubbles.
static constexpr int TILE_M  = 128;
static constexpr int TILE_N  = 128;
static constexpr int KSTAGE  = 64;                   // K elems per stage (128 B/row)
static constexpr int NCHUNK  = K_TOTAL / KSTAGE;     // 16
static constexpr int NSTAGES = 3;
static constexpr int THREADS = 256;                  // 8 warps

// SMEM: bf16 tiles, rows padded 128B -> 144B (9x16B stride => conflict-free ldmatrix)
static constexpr int ROW_B   = 144;
static constexpr int A_STAGE = TILE_M * ROW_B;       // 18432 B
static constexpr int B_STAGE = TILE_N * ROW_B;       // 18432 B
static constexpr int SM_B0   = NSTAGES * A_STAGE;
static constexpr int SM_BYTES = NSTAGES * (A_STAGE + B_STAGE);  // 110592 B (x2 <= 228K)

DI uint32_t smem_u32(const void* p) {
    uint32_t a;
    asm("{ .reg .u64 t; cvta.to.shared.u64 t, %1; cvt.u32.u64 %0, t; }" : "=r"(a) : "l"(p));
    return a;
}
DI void cp16(uint32_t dst, const void* src) {
    asm volatile("cp.async.cg.shared.global [%0], [%1], 16;" :: "r"(dst), "l"(src));
}
#define CP_COMMIT() asm volatile("cp.async.commit_group;" ::: "memory")
#define CP_WAIT1()  asm volatile("cp.async.wait_group 1;" ::: "memory")

#define LDSM4(r0, r1, r2, r3, addr) \
    asm volatile("ldmatrix.sync.aligned.m8n8.x4.shared.b16 {%0,%1,%2,%3}, [%4];" \
                 : "=r"(r0), "=r"(r1), "=r"(r2), "=r"(r3) : "r"(addr))

#define MMA_BF16(c, a0, a1, a2, a3, b0, b1) \
    asm volatile( \
        "mma.sync.aligned.m16n8k16.row.col.f32.bf16.bf16.f32 " \
        "{%0,%1,%2,%3}, {%4,%5,%6,%7}, {%8,%9}, {%0,%1,%2,%3};" \
        : "+f"((c)[0]), "+f"((c)[1]), "+f"((c)[2]), "+f"((c)[3]) \
        : "r"(a0), "r"(a1), "r"(a2), "r"(a3), "r"(b0), "r"(b1))

// ---------------- Pack pre-pass: int32 -> bf16, 8 elements/thread ----------------
DI uint32_t bf16x2_from_ints(int lo, int hi) {
    uint32_t r;
    asm("cvt.rn.bf16x2.f32 %0, %1, %2;" : "=r"(r) : "f"((float)hi), "f"((float)lo));
    return r;
}
DI uint4 pack8(const int4* p) {
    int4 v0 = p[0], v1 = p[1];
    uint4 o;
    o.x = bf16x2_from_ints(v0.x, v0.y);
    o.y = bf16x2_from_ints(v0.z, v0.w);
    o.z = bf16x2_from_ints(v1.x, v1.y);
    o.w = bf16x2_from_ints(v1.z, v1.w);
    return o;
}
__global__ void pack_both(const int4* __restrict__ xs, const int4* __restrict__ ws,
                          uint16_t* __restrict__ xd, uint16_t* __restrict__ wd,
                          int n8x, int n8w) {
    int i = blockIdx.x * blockDim.x + threadIdx.x;
    if (i < n8w) {
        reinterpret_cast<uint4*>(wd)[i] = pack8(ws + (size_t)i * 2);
    } else if (i - n8w < n8x) {
        int j = i - n8w;
        reinterpret_cast<uint4*>(xd)[j] = pack8(xs + (size_t)j * 2);
    }
}

// Load one K-stage: A 128 rows + B 128 rows, 128B/row, via cp.async (4+4 per thread).
DI void load_stage(const uint16_t* __restrict__ x, const uint16_t* __restrict__ w,
                   int m0, int n0, int kc, uint32_t sbase, int stage, int tid) {
    const uint32_t smA = sbase + stage * A_STAGE;
    const uint32_t smB = sbase + SM_B0 + stage * B_STAGE;
    const int k0 = kc * KSTAGE;
#pragma unroll
    for (int i = 0; i < 4; i++) {                    // A: 1024 16B-chunks, 4/thread
        int u = tid + i * THREADS;
        int row = u >> 3, c = u & 7;
        cp16(smA + row * ROW_B + c * 16, x + (size_t)(m0 + row) * K_TOTAL + k0 + c * 8);
    }
#pragma unroll
    for (int i = 0; i < 4; i++) {                    // B: 1024 16B-chunks, 4/thread
        int u = tid + i * THREADS;
        int row = u >> 3, c = u & 7;
        cp16(smB + row * ROW_B + c * 16, w + (size_t)(n0 + row) * K_TOTAL + k0 + c * 8);
    }
}

__global__ void __launch_bounds__(THREADS, 2)
qgemm_hmma_kernel(const float* __restrict__ scale_i, const float* __restrict__ scale_w,
                  const float* __restrict__ bias, float* __restrict__ out) {
    extern __shared__ char smem[];
    const uint16_t* __restrict__ x = g_xh;
    const uint16_t* __restrict__ w = g_wh;
    const uint32_t sbase = smem_u32(smem);
    const int tid = threadIdx.x;
    const int lane = tid & 31;
    const int wid = tid >> 5;
    const int warp_m = wid & 3;        // 4 warps along M: 32 rows each
    const int warp_n = wid >> 2;       // 2 warps along N: 64 cols each
    const int m0 = blockIdx.y * TILE_M;
    const int n0 = blockIdx.x * TILE_N;

    const int tg = lane >> 2;          // groupID (0..7)
    const int tc = lane & 3;           // threadID_in_group

    float acc[2][8][4];
#pragma unroll
    for (int mt = 0; mt < 2; mt++)
#pragma unroll
        for (int nt = 0; nt < 8; nt++)
#pragma unroll
            for (int j = 0; j < 4; j++) acc[mt][nt][j] = 0.0f;

    // ldmatrix lane addressing (within a stage, before k-step offset):
    // A x4: [rows 0-7, k0-7][rows 8-15, k0-7][rows 0-7, k8-15][rows 8-15, k8-15]
    const int am = lane >> 3;
    const uint32_t aOff = (uint32_t)(warp_m * 32 + (am & 1) * 8 + (lane & 7)) * ROW_B
                        + (uint32_t)(am >> 1) * 16;
    // B x4 per n-tile pair p: [n 0-7, k0-7][n 0-7, k8-15][n 8-15, k0-7][n 8-15, k8-15]
    const uint32_t bOff = (uint32_t)(warp_n * 64 + (am >> 1) * 8 + (lane & 7)) * ROW_B
                        + (uint32_t)(am & 1) * 16;

    // Prologue: stages 0,1 in flight
    load_stage(x, w, m0, n0, 0, sbase, 0, tid); CP_COMMIT();
    load_stage(x, w, m0, n0, 1, sbase, 1, tid); CP_COMMIT();

#pragma unroll 1
    for (int kc = 0; kc < NCHUNK; kc++) {
        CP_WAIT1();                    // stage kc resident
        __syncthreads();               // all warps done with stage (kc+2)%3's old data
        if (kc + 2 < NCHUNK)
            load_stage(x, w, m0, n0, kc + 2, sbase, (kc + 2) % NSTAGES, tid);
        CP_COMMIT();

        const int stage = kc % NSTAGES;
        const uint32_t aS = sbase + stage * A_STAGE + aOff;
        const uint32_t bS = sbase + SM_B0 + stage * B_STAGE + bOff;
#pragma unroll
        for (int ks = 0; ks < 4; ks++) {           // four k=16 steps per stage
            const uint32_t ko = ks * 32;           // 16 bf16 = 32 bytes
            // Flat named fragments; explicitly peeled copy-free B double-buffer:
            // LDSM for pair p+1 is in flight while the 4 MMAs of pair p issue.
            uint32_t a00, a01, a02, a03, a10, a11, a12, a13;
            uint32_t e0, e1, e2, e3;               // even-parity B buffer (p=0,2)
            uint32_t o0, o1, o2, o3;               // odd-parity  B buffer (p=1,3)
            LDSM4(a00, a01, a02, a03, aS + ko);
            LDSM4(a10, a11, a12, a13, aS + 16 * ROW_B + ko);
            LDSM4(e0, e1, e2, e3, bS + ko);                       // p=0
            LDSM4(o0, o1, o2, o3, bS + 16 * ROW_B + ko);          // prefetch p=1
            MMA_BF16(acc[0][0], a00, a01, a02, a03, e0, e1);      // p=0 consumes even
            MMA_BF16(acc[1][0], a10, a11, a12, a13, e0, e1);
            MMA_BF16(acc[0][1], a00, a01, a02, a03, e2, e3);
            MMA_BF16(acc[1][1], a10, a11, a12, a13, e2, e3);
            LDSM4(e0, e1, e2, e3, bS + 32 * ROW_B + ko);          // prefetch p=2
            MMA_BF16(acc[0][2], a00, a01, a02, a03, o0, o1);      // p=1 consumes odd
            MMA_BF16(acc[1][2], a10, a11, a12, a13, o0, o1);
            MMA_BF16(acc[0][3], a00, a01, a02, a03, o2, o3);
            MMA_BF16(acc[1][3], a10, a11, a12, a13, o2, o3);
            LDSM4(o0, o1, o2, o3, bS + 48 * ROW_B + ko);          // prefetch p=3
            MMA_BF16(acc[0][4], a00, a01, a02, a03, e0, e1);      // p=2 consumes even
            MMA_BF16(acc[1][4], a10, a11, a12, a13, e0, e1);
            MMA_BF16(acc[0][5], a00, a01, a02, a03, e2, e3);
            MMA_BF16(acc[1][5], a10, a11, a12, a13, e2, e3);
            MMA_BF16(acc[0][6], a00, a01, a02, a03, o0, o1);      // p=3 consumes odd
            MMA_BF16(acc[1][6], a10, a11, a12, a13, o0, o1);
            MMA_BF16(acc[0][7], a00, a01, a02, a03, o2, o3);
            MMA_BF16(acc[1][7], a10, a11, a12, a13, o2, o3);
        }
    }

    // Epilogue: out = acc * (scale_i * scale_w[n]) + bias[n]  (acc holds exact integers)
    const float si = __ldg(scale_i);
    const int row0 = m0 + warp_m * 32 + tg;
    const int col0 = n0 + warp_n * 64 + tc * 2;
#pragma unroll
    for (int nt = 0; nt < 8; nt++) {
        const int c = col0 + nt * 8;
        const float2 sw = __ldg(reinterpret_cast<const float2*>(scale_w + c));
        const float2 bb = __ldg(reinterpret_cast<const float2*>(bias + c));
        const float s0 = si * sw.x, s1 = si * sw.y;
#pragma unroll
        for (int mt = 0; mt < 2; mt++) {
            const int r = row0 + mt * 16;
            float2 v0, v1;
            v0.x = fmaf(acc[mt][nt][0], s0, bb.x);
            v0.y = fmaf(acc[mt][nt][1], s1, bb.y);
            v1.x = fmaf(acc[mt][nt][2], s0, bb.x);
            v1.y = fmaf(acc[mt][nt][3], s1, bb.y);
            *reinterpret_cast<float2*>(out + (size_t)r * N_TOTAL + c)       = v0;
            *reinterpret_cast<float2*>(out + (size_t)(r + 8) * N_TOTAL + c) = v1;
        }
    }
}

extern "C" void kernel_launch(void* const* d_in, const int* in_sizes, int n_in,
                              void* d_out, int out_size) {
    // Harness promotes int8 jax arrays to int32 buffers.
    const int4* x32 = (const int4*)d_in[0];      // [8192,1024] int32 (int8 values)
    const int4* w32 = (const int4*)d_in[1];      // [4096,1024] int32
    const float* si = (const float*)d_in[2];     // scalar f32
    const float* sw = (const float*)d_in[3];     // [4096] f32
    const float* bi = (const float*)d_in[4];     // [4096] f32
    float* out = (float*)d_out;                  // [8192,4096] f32

    uint16_t *dxh = nullptr, *dwh = nullptr;
    cudaGetSymbolAddress((void**)&dxh, g_xh);
    cudaGetSymbolAddress((void**)&dwh, g_wh);

    {
        int n8x = (M_TOTAL * K_TOTAL) / 8;       // 1048576
        int n8w = (N_TOTAL * K_TOTAL) / 8;       // 524288
        int total = n8x + n8w;
        pack_both<<<(total + 255) / 256, 256>>>(x32, w32, dxh, dwh, n8x, n8w);
    }

    cudaFuncSetAttribute(qgemm_hmma_kernel,
                         cudaFuncAttributeMaxDynamicSharedMemorySize, SM_BYTES);
    dim3 grid(N_TOTAL / TILE_N, M_TOTAL / TILE_M);  // (32, 64)
    qgemm_hmma_kernel<<<grid, THREADS, SM_BYTES, 0>>>(si, sw, bi, out);
}